// round 16
// baseline (speedup 1.0000x reference)
#include <cuda_runtime.h>
#include <cuda_bf16.h>
#include <cstdint>

// ---------------------------------------------------------------------------
// GMDTW (soft-DTW, gamma=1), m1=m2=2048, d=128. log2-domain DP.
// R16 = R15 with the redundant-row diag-carry fixed: ut must become the
// CONSUMED sh (row 2L-1 @ k-1), not rtold. Restores bit-exact row duplication.
// ---------------------------------------------------------------------------

#define M1 2048
#define M2 2048
#define DIM 128
#define NCTA 32
#define CPITCH 2080          // floats per diagonal row of Cd
#define CROWS  4176          // diagonal rows incl. staging overrun pad
#define BIGF 1e30f
#define INV_LN2 1.44269504088896340736f
#define LN2F    0.69314718055994530942f

__device__ float g_Cd[(size_t)CROWS * CPITCH];  // Cd[k][r] = C[r][k-r-2]*INV_LN2
__device__ float g_n1[M1];
__device__ float g_n2[M2];
__device__ float g_bnd[NCTA][4240];             // g_bnd[w][k] = R~[row 64(w+1)] @ diag k
__device__ int   g_prog[NCTA * 32];             // flag per 128B

__device__ __forceinline__ float ex2f(float x) {
    float r; asm("ex2.approx.f32 %0, %1;" : "=f"(r) : "f"(x)); return r;
}
__device__ __forceinline__ float lg2f(float x) {
    float r; asm("lg2.approx.f32 %0, %1;" : "=f"(r) : "f"(x)); return r;
}
__device__ __forceinline__ int acq_load(const int* p) {
    int v; asm volatile("ld.global.acquire.gpu.b32 %0, [%1];" : "=r"(v) : "l"(p) : "memory");
    return v;
}
__device__ __forceinline__ void rel_store(int* p, int v) {
    asm volatile("st.global.release.gpu.b32 [%0], %1;" :: "l"(p), "r"(v) : "memory");
}
__device__ __forceinline__ float4 ldcg4(const float* p) {
    float4 v;
    asm volatile("ld.global.cg.v4.f32 {%0,%1,%2,%3}, [%4];"
                 : "=f"(v.x), "=f"(v.y), "=f"(v.z), "=f"(v.w) : "l"(p) : "memory");
    return v;
}
__device__ __forceinline__ void stcg4(float* p, float4 v) {
    asm volatile("st.global.cg.v4.f32 [%0], {%1,%2,%3,%4};"
                 :: "l"(p), "f"(v.x), "f"(v.y), "f"(v.z), "f"(v.w) : "memory");
}
// softmin (log2 domain, gamma=1): m + lg2(1 + 2^(m-x) + 2^(m-y)),
// {m,x,y} = sorted(a,b,c) — identical arithmetic for identical inputs.
__device__ __forceinline__ float softmin3(float a, float b, float c, float cost) {
    float w = fminf(a, b), x = fmaxf(a, b);
    float m = fminf(w, c), y = fmaxf(w, c);
    float e = ex2f(m - x) + ex2f(m - y);
    float t = lg2f(1.0f + e);
    return (cost + m) - t;
}

// ---------------------------------------------------------------------------
__global__ void __launch_bounds__(1024) initc_k() {
    size_t idx = (size_t)blockIdx.x * 1024 + threadIdx.x;
    const size_t n4 = (size_t)CROWS * CPITCH / 4;
    if (idx < n4) {
        ((float4*)g_Cd)[idx] = make_float4(BIGF, BIGF, BIGF, BIGF);
    }
    if (idx < NCTA * 32) g_prog[idx] = 0;
}

__global__ void __launch_bounds__(256) norms_k(const float* __restrict__ y,
                                               const float* __restrict__ x2) {
    int w = blockIdx.x * 8 + (threadIdx.x >> 5);
    int lane = threadIdx.x & 31;
    if (w >= 2 * M1) return;
    const float* src = (w < M1) ? (y + (size_t)w * DIM) : (x2 + (size_t)(w - M1) * DIM);
    float4 v = ((const float4*)src)[lane];
    float s = v.x * v.x + v.y * v.y + v.z * v.z + v.w * v.w;
#pragma unroll
    for (int o = 16; o; o >>= 1) s += __shfl_xor_sync(0xffffffffu, s, o);
    if (lane == 0) {
        if (w < M1) g_n1[w] = s; else g_n2[w - M1] = s;
    }
}

// GEMM with diagonal-major scatter epilogue: (r,c) -> Cd[r+c+2][r]
__global__ void __launch_bounds__(256) gemm_k(const float* __restrict__ A,
                                              const float* __restrict__ B) {
    __shared__ float As[32][68];
    __shared__ float Bs[32][68];
    const int t  = threadIdx.x;
    const int tx = t & 15, ty = t >> 4;
    const int bi = blockIdx.y << 6, bj = blockIdx.x << 6;
    const int lrow = t >> 2;
    const int lk   = (t & 3) << 3;

    float acc[4][4];
#pragma unroll
    for (int u = 0; u < 4; ++u)
#pragma unroll
        for (int v = 0; v < 4; ++v) acc[u][v] = 0.0f;

    const float* Ap = A + (size_t)(bi + lrow) * DIM + lk;
    const float* Bp = B + (size_t)(bj + lrow) * DIM + lk;

    for (int k0 = 0; k0 < DIM; k0 += 32) {
        float4 a0 = *(const float4*)(Ap + k0);
        float4 a1 = *(const float4*)(Ap + k0 + 4);
        float4 b0 = *(const float4*)(Bp + k0);
        float4 b1 = *(const float4*)(Bp + k0 + 4);
        __syncthreads();
        As[lk + 0][lrow] = a0.x; As[lk + 1][lrow] = a0.y;
        As[lk + 2][lrow] = a0.z; As[lk + 3][lrow] = a0.w;
        As[lk + 4][lrow] = a1.x; As[lk + 5][lrow] = a1.y;
        As[lk + 6][lrow] = a1.z; As[lk + 7][lrow] = a1.w;
        Bs[lk + 0][lrow] = b0.x; Bs[lk + 1][lrow] = b0.y;
        Bs[lk + 2][lrow] = b0.z; Bs[lk + 3][lrow] = b0.w;
        Bs[lk + 4][lrow] = b1.x; Bs[lk + 5][lrow] = b1.y;
        Bs[lk + 6][lrow] = b1.z; Bs[lk + 7][lrow] = b1.w;
        __syncthreads();
#pragma unroll
        for (int kk = 0; kk < 32; ++kk) {
            float4 av = *(const float4*)&As[kk][ty << 2];
            float4 bv = *(const float4*)&Bs[kk][tx << 2];
            float a_[4] = {av.x, av.y, av.z, av.w};
            float b_[4] = {bv.x, bv.y, bv.z, bv.w};
#pragma unroll
            for (int u = 0; u < 4; ++u)
#pragma unroll
                for (int v = 0; v < 4; ++v) acc[u][v] += a_[u] * b_[v];
        }
    }

    float4 nb = *(const float4*)&g_n2[bj + (tx << 2)];
#pragma unroll
    for (int u = 0; u < 4; ++u) {
        int r = bi + (ty << 2) + u;
        float na = g_n1[r];
        float o0 = (na + nb.x - 2.0f * acc[u][0]) * INV_LN2;
        float o1 = (na + nb.y - 2.0f * acc[u][1]) * INV_LN2;
        float o2 = (na + nb.z - 2.0f * acc[u][2]) * INV_LN2;
        float o3 = (na + nb.w - 2.0f * acc[u][3]) * INV_LN2;
        int c = bj + (tx << 2);
        g_Cd[(size_t)(r + c + 2) * CPITCH + r] = o0;
        g_Cd[(size_t)(r + c + 3) * CPITCH + r] = o1;
        g_Cd[(size_t)(r + c + 4) * CPITCH + r] = o2;
        g_Cd[(size_t)(r + c + 5) * CPITCH + r] = o3;
    }
}

// ---------------------------------------------------------------------------
// DP wavefront: 32 CTAs x 2 warps (compute + helper), 64 useful rows/CTA.
// Lane L: redundant row rt = base+2L (bit-exact dup of left neighbor's rB),
//         useful rows rA = base+2L+1, rB = base+2L+2. Shfl feeds only rt.
__global__ void __launch_bounds__(64, 1) dp_k(float* __restrict__ out) {
    const int cta  = blockIdx.x;
    const int tid  = threadIdx.x;
    const int wid  = tid >> 5;
    const int lane = tid & 31;
    const int base = cta * 64;

    __shared__ __align__(16) float  cbuf[2][16][64];  // costs, double-buffered
    __shared__ __align__(16) float4 sbch[2][5];       // boundary chunks (20 floats)
    __shared__ __align__(16) float  obuf[2][16];      // boundary outputs

    const float4 BIG4 = make_float4(BIGF, BIGF, BIGF, BIGF);

    const int  wend    = (cta > 0) ? (base + 2048) : -1;
    const int  flagmax = wend + 3;
    int*       myflag  = &g_prog[cta * 32];
    const int* pflag   = &g_prog[((cta > 0) ? (cta - 1) : 0) * 32];
    const float* brow  = g_bnd[(cta > 0) ? (cta - 1) : 0];

    // helper staging geometry
    const int ph = lane >> 4;              // 0/1
    const int qf = (lane & 15) << 2;       // float4 column

    // compute-warp state — invariants at top of iteration computing diag k:
    //   rt = row(2L)   @ k-1,  ut = row(2L-1) @ k-2
    //   rA = row(2L+1) @ k-1,  uA = row(2L)   @ k-2
    //   rB = row(2L+2) @ k-1,  uB = row(2L+1) @ k-2
    //   sh = row(2L-1) @ k-1
    float rt = BIGF, ut = BIGF;
    float rA = BIGF, uA = BIGF;
    float rB = BIGF, uB = BIGF;
    float sh = BIGF;
    float res = BIGF;
    int known = -1000000;                  // helper flag cache

    // ---- prologue (helper stages group 0) ----
    if (wid == 1) {
        const float* src = g_Cd + (size_t)base * CPITCH + base + qf;
#pragma unroll
        for (int j = 0; j < 8; ++j) {
            float4 v = __ldg((const float4*)(src + (size_t)(2 * j + ph) * CPITCH));
            *(float4*)&cbuf[0][2 * j + ph][qf] = v;
        }
        if (cta > 0) {
            int need = min(base + 15, flagmax);
            do { known = acq_load(pflag); } while (known < need);
        }
        if (lane < 5) {
            int cs = base - 4 + 4 * lane;
            sbch[0][lane] = (cta > 0 && cs <= wend) ? ldcg4(brow + cs) : BIG4;
        }
        if (cta == 0 && lane == 0)
            ((float*)&sbch[0][0])[4] = 0.0f;   // virtual B[base+0] = R[0][0] = 0
    }
    __syncthreads();

    const bool l0  = (lane == 0);
    const bool l31 = (lane == 31);
    // cost columns: rt -> 2L-1 (clamped for lane0; value discarded there),
    //               rA/rB pair -> float2 at 2L
    const int ccR = l0 ? 0 : (2 * lane - 1);
    const int cc2 = 2 * lane;

    // lane0 carry init: rt = B[base-1] (feeds rA's up at k=base)
    if (wid == 0 && l0) {
        const float* b0 = (const float*)&sbch[0][0];
        rt = b0[3];                         // B[base-1]
        ut = b0[2];                         // B[base-2] (unused for lane0)
    }

    int g = base;
#pragma unroll 1
    for (int gi = 0; gi < 133; ++gi, g += 16) {
        const int a = gi & 1;
        const int b = a ^ 1;

        if (wid == 0) {
            // ================= COMPUTE WARP =================
            const float* crd = &cbuf[a][0][0];
            const float* bb  = ((const float*)&sbch[a][0]) + 4;  // bb[p] = B[g+p]
            float  cRn = crd[ccR];
            float2 c2n = *(const float2*)(crd + cc2);
            float  bbn = bb[0];
            float  qv[16];

#pragma unroll
            for (int p = 0; p < 16; ++p) {
                float  cR = cRn;
                float2 c2 = c2n;
                float  bk = bbn;
                if (p < 15) {
                    cRn = crd[(p + 1) * 64 + ccR];
                    c2n = *(const float2*)(crd + (p + 1) * 64 + cc2);
                    bbn = bb[p + 1];
                }

                float rtold = rt;
                float rAold = rA;
                float shold = sh;

                // useful rows first (neighbors same-lane)
                rA = softmin3(rtold, rA, uA, c2.x);
                float shnew = __shfl_up_sync(0xffffffffu, rA, 1);  // for next iter
                rB = softmin3(rAold, rB, uB, c2.y);

                // redundant row (consumes sh/ut = row 2L-1 @ k-1 / k-2)
                float rtnew = softmin3(shold, rtold, ut, cR);
                rt = l0 ? bk : rtnew;       // lane0: boundary row = published value

                uA = rtold;
                uB = rAold;
                ut = shold;                 // FIX: diag carry = consumed sh
                sh = shnew;

                qv[p] = rB;
            }

            if (gi == 132) res = qv[0];     // k = base+2112 (cta31: R[2048][2048])

            if (l31) {
                *(float4*)&obuf[a][0]  = make_float4(qv[0],  qv[1],  qv[2],  qv[3]);
                *(float4*)&obuf[a][4]  = make_float4(qv[4],  qv[5],  qv[6],  qv[7]);
                *(float4*)&obuf[a][8]  = make_float4(qv[8],  qv[9],  qv[10], qv[11]);
                *(float4*)&obuf[a][12] = make_float4(qv[12], qv[13], qv[14], qv[15]);
            }
        } else {
            // ================= HELPER WARP =================
            const int gnext = g + 16;
            // 1. publish group gi-1 (lane 0: release orders own prior stores)
            if (gi > 0 && lane == 0) {
                int gp = g - 16;
                float4 o0 = *(float4*)&obuf[b][0];
                float4 o1 = *(float4*)&obuf[b][4];
                float4 o2 = *(float4*)&obuf[b][8];
                float4 o3 = *(float4*)&obuf[b][12];
                stcg4(&g_bnd[cta][gp],      o0);
                stcg4(&g_bnd[cta][gp + 4],  o1);
                stcg4(&g_bnd[cta][gp + 8],  o2);
                stcg4(&g_bnd[cta][gp + 12], o3);
                rel_store(myflag, gp + 15);
            }
            // 2. cost LDGs for group gi+1
            const float* src = g_Cd + (size_t)gnext * CPITCH + base + qf;
            float4 tv[8];
#pragma unroll
            for (int j = 0; j < 8; ++j)
                tv[j] = __ldg((const float4*)(src + (size_t)(2 * j + ph) * CPITCH));
            // 3. acquire spin (off the critical warp)
            if (cta > 0) {
                int need = min(gnext + 15, flagmax);
                while (known < need) known = acq_load(pflag);
            }
            // 4. boundary chunks for gi+1
            if (lane < 5) {
                int cs = gnext - 4 + 4 * lane;
                sbch[b][lane] = (cta > 0 && cs <= wend) ? ldcg4(brow + cs) : BIG4;
            }
            // 5. STS costs
#pragma unroll
            for (int j = 0; j < 8; ++j)
                *(float4*)&cbuf[b][2 * j + ph][qf] = tv[j];
        }

        __syncthreads();
    }

    // epilogue: publish final group (132, in obuf[0]) for the successor
    if (wid == 1 && lane == 0) {
        int gp = base + 16 * 132;
        float4 o0 = *(float4*)&obuf[0][0];
        float4 o1 = *(float4*)&obuf[0][4];
        float4 o2 = *(float4*)&obuf[0][8];
        float4 o3 = *(float4*)&obuf[0][12];
        stcg4(&g_bnd[cta][gp],      o0);
        stcg4(&g_bnd[cta][gp + 4],  o1);
        stcg4(&g_bnd[cta][gp + 8],  o2);
        stcg4(&g_bnd[cta][gp + 12], o3);
        rel_store(myflag, gp + 15);
    }

    if (wid == 0 && cta == NCTA - 1 && l31) {
        out[0] = res * LN2F;
    }
}

// ---------------------------------------------------------------------------
extern "C" void kernel_launch(void* const* d_in, const int* in_sizes, int n_in,
                              void* d_out, int out_size) {
    const float* y  = (const float*)d_in[0];
    const float* x2 = (const float*)d_in[1];
    float* out = (float*)d_out;

    const int n4 = (CROWS * CPITCH) / 4;
    initc_k<<<(n4 + 1023) / 1024, 1024>>>();
    norms_k<<<512, 256>>>(y, x2);
    gemm_k<<<dim3(M2 / 64, M1 / 64), 256>>>(y, x2);
    dp_k<<<NCTA, 64>>>(out);
}

// round 17
// speedup vs baseline: 1.0411x; 1.0411x over previous
#include <cuda_runtime.h>
#include <cuda_bf16.h>
#include <cstdint>

// ---------------------------------------------------------------------------
// GMDTW (soft-DTW, gamma=1), m1=m2=2048, d=128. log2-domain DP.
// R17 = R16 with the compute-warp inner body phase-batched across the three
// row-streams (all mins, all subs, all ex2, all sums, all lg2, all finals)
// to force cross-row ILP; per-row dataflow unchanged (bit-exact).
// ---------------------------------------------------------------------------

#define M1 2048
#define M2 2048
#define DIM 128
#define NCTA 32
#define CPITCH 2080          // floats per diagonal row of Cd
#define CROWS  4176          // diagonal rows incl. staging overrun pad
#define BIGF 1e30f
#define INV_LN2 1.44269504088896340736f
#define LN2F    0.69314718055994530942f

__device__ float g_Cd[(size_t)CROWS * CPITCH];  // Cd[k][r] = C[r][k-r-2]*INV_LN2
__device__ float g_n1[M1];
__device__ float g_n2[M2];
__device__ float g_bnd[NCTA][4240];             // g_bnd[w][k] = R~[row 64(w+1)] @ diag k
__device__ int   g_prog[NCTA * 32];             // flag per 128B

__device__ __forceinline__ float ex2f(float x) {
    float r; asm("ex2.approx.f32 %0, %1;" : "=f"(r) : "f"(x)); return r;
}
__device__ __forceinline__ float lg2f(float x) {
    float r; asm("lg2.approx.f32 %0, %1;" : "=f"(r) : "f"(x)); return r;
}
__device__ __forceinline__ int acq_load(const int* p) {
    int v; asm volatile("ld.global.acquire.gpu.b32 %0, [%1];" : "=r"(v) : "l"(p) : "memory");
    return v;
}
__device__ __forceinline__ void rel_store(int* p, int v) {
    asm volatile("st.global.release.gpu.b32 [%0], %1;" :: "l"(p), "r"(v) : "memory");
}
__device__ __forceinline__ float4 ldcg4(const float* p) {
    float4 v;
    asm volatile("ld.global.cg.v4.f32 {%0,%1,%2,%3}, [%4];"
                 : "=f"(v.x), "=f"(v.y), "=f"(v.z), "=f"(v.w) : "l"(p) : "memory");
    return v;
}
__device__ __forceinline__ void stcg4(float* p, float4 v) {
    asm volatile("st.global.cg.v4.f32 [%0], {%1,%2,%3,%4};"
                 :: "l"(p), "f"(v.x), "f"(v.y), "f"(v.z), "f"(v.w) : "memory");
}

// ---------------------------------------------------------------------------
__global__ void __launch_bounds__(1024) initc_k() {
    size_t idx = (size_t)blockIdx.x * 1024 + threadIdx.x;
    const size_t n4 = (size_t)CROWS * CPITCH / 4;
    if (idx < n4) {
        ((float4*)g_Cd)[idx] = make_float4(BIGF, BIGF, BIGF, BIGF);
    }
    if (idx < NCTA * 32) g_prog[idx] = 0;
}

__global__ void __launch_bounds__(256) norms_k(const float* __restrict__ y,
                                               const float* __restrict__ x2) {
    int w = blockIdx.x * 8 + (threadIdx.x >> 5);
    int lane = threadIdx.x & 31;
    if (w >= 2 * M1) return;
    const float* src = (w < M1) ? (y + (size_t)w * DIM) : (x2 + (size_t)(w - M1) * DIM);
    float4 v = ((const float4*)src)[lane];
    float s = v.x * v.x + v.y * v.y + v.z * v.z + v.w * v.w;
#pragma unroll
    for (int o = 16; o; o >>= 1) s += __shfl_xor_sync(0xffffffffu, s, o);
    if (lane == 0) {
        if (w < M1) g_n1[w] = s; else g_n2[w - M1] = s;
    }
}

// GEMM with diagonal-major scatter epilogue: (r,c) -> Cd[r+c+2][r]
__global__ void __launch_bounds__(256) gemm_k(const float* __restrict__ A,
                                              const float* __restrict__ B) {
    __shared__ float As[32][68];
    __shared__ float Bs[32][68];
    const int t  = threadIdx.x;
    const int tx = t & 15, ty = t >> 4;
    const int bi = blockIdx.y << 6, bj = blockIdx.x << 6;
    const int lrow = t >> 2;
    const int lk   = (t & 3) << 3;

    float acc[4][4];
#pragma unroll
    for (int u = 0; u < 4; ++u)
#pragma unroll
        for (int v = 0; v < 4; ++v) acc[u][v] = 0.0f;

    const float* Ap = A + (size_t)(bi + lrow) * DIM + lk;
    const float* Bp = B + (size_t)(bj + lrow) * DIM + lk;

    for (int k0 = 0; k0 < DIM; k0 += 32) {
        float4 a0 = *(const float4*)(Ap + k0);
        float4 a1 = *(const float4*)(Ap + k0 + 4);
        float4 b0 = *(const float4*)(Bp + k0);
        float4 b1 = *(const float4*)(Bp + k0 + 4);
        __syncthreads();
        As[lk + 0][lrow] = a0.x; As[lk + 1][lrow] = a0.y;
        As[lk + 2][lrow] = a0.z; As[lk + 3][lrow] = a0.w;
        As[lk + 4][lrow] = a1.x; As[lk + 5][lrow] = a1.y;
        As[lk + 6][lrow] = a1.z; As[lk + 7][lrow] = a1.w;
        Bs[lk + 0][lrow] = b0.x; Bs[lk + 1][lrow] = b0.y;
        Bs[lk + 2][lrow] = b0.z; Bs[lk + 3][lrow] = b0.w;
        Bs[lk + 4][lrow] = b1.x; Bs[lk + 5][lrow] = b1.y;
        Bs[lk + 6][lrow] = b1.z; Bs[lk + 7][lrow] = b1.w;
        __syncthreads();
#pragma unroll
        for (int kk = 0; kk < 32; ++kk) {
            float4 av = *(const float4*)&As[kk][ty << 2];
            float4 bv = *(const float4*)&Bs[kk][tx << 2];
            float a_[4] = {av.x, av.y, av.z, av.w};
            float b_[4] = {bv.x, bv.y, bv.z, bv.w};
#pragma unroll
            for (int u = 0; u < 4; ++u)
#pragma unroll
                for (int v = 0; v < 4; ++v) acc[u][v] += a_[u] * b_[v];
        }
    }

    float4 nb = *(const float4*)&g_n2[bj + (tx << 2)];
#pragma unroll
    for (int u = 0; u < 4; ++u) {
        int r = bi + (ty << 2) + u;
        float na = g_n1[r];
        float o0 = (na + nb.x - 2.0f * acc[u][0]) * INV_LN2;
        float o1 = (na + nb.y - 2.0f * acc[u][1]) * INV_LN2;
        float o2 = (na + nb.z - 2.0f * acc[u][2]) * INV_LN2;
        float o3 = (na + nb.w - 2.0f * acc[u][3]) * INV_LN2;
        int c = bj + (tx << 2);
        g_Cd[(size_t)(r + c + 2) * CPITCH + r] = o0;
        g_Cd[(size_t)(r + c + 3) * CPITCH + r] = o1;
        g_Cd[(size_t)(r + c + 4) * CPITCH + r] = o2;
        g_Cd[(size_t)(r + c + 5) * CPITCH + r] = o3;
    }
}

// ---------------------------------------------------------------------------
// DP wavefront: 32 CTAs x 2 warps (compute + helper), 64 useful rows/CTA.
// Lane L: redundant row rt = base+2L (bit-exact dup of left neighbor's rB),
//         useful rows rA = base+2L+1, rB = base+2L+2. Shfl feeds only rt.
__global__ void __launch_bounds__(64, 1) dp_k(float* __restrict__ out) {
    const int cta  = blockIdx.x;
    const int tid  = threadIdx.x;
    const int wid  = tid >> 5;
    const int lane = tid & 31;
    const int base = cta * 64;

    __shared__ __align__(16) float  cbuf[2][16][64];  // costs, double-buffered
    __shared__ __align__(16) float4 sbch[2][5];       // boundary chunks (20 floats)
    __shared__ __align__(16) float  obuf[2][16];      // boundary outputs

    const float4 BIG4 = make_float4(BIGF, BIGF, BIGF, BIGF);

    const int  wend    = (cta > 0) ? (base + 2048) : -1;
    const int  flagmax = wend + 3;
    int*       myflag  = &g_prog[cta * 32];
    const int* pflag   = &g_prog[((cta > 0) ? (cta - 1) : 0) * 32];
    const float* brow  = g_bnd[(cta > 0) ? (cta - 1) : 0];

    // helper staging geometry
    const int ph = lane >> 4;              // 0/1
    const int qf = (lane & 15) << 2;       // float4 column

    // compute-warp state — invariants at top of iteration computing diag k:
    //   rt = row(2L)   @ k-1,  ut = row(2L-1) @ k-2
    //   rA = row(2L+1) @ k-1,  uA = row(2L)   @ k-2
    //   rB = row(2L+2) @ k-1,  uB = row(2L+1) @ k-2
    //   sh = row(2L-1) @ k-1
    float rt = BIGF, ut = BIGF;
    float rA = BIGF, uA = BIGF;
    float rB = BIGF, uB = BIGF;
    float sh = BIGF;
    float res = BIGF;
    int known = -1000000;                  // helper flag cache

    // ---- prologue (helper stages group 0) ----
    if (wid == 1) {
        const float* src = g_Cd + (size_t)base * CPITCH + base + qf;
#pragma unroll
        for (int j = 0; j < 8; ++j) {
            float4 v = __ldg((const float4*)(src + (size_t)(2 * j + ph) * CPITCH));
            *(float4*)&cbuf[0][2 * j + ph][qf] = v;
        }
        if (cta > 0) {
            int need = min(base + 15, flagmax);
            do { known = acq_load(pflag); } while (known < need);
        }
        if (lane < 5) {
            int cs = base - 4 + 4 * lane;
            sbch[0][lane] = (cta > 0 && cs <= wend) ? ldcg4(brow + cs) : BIG4;
        }
        if (cta == 0 && lane == 0)
            ((float*)&sbch[0][0])[4] = 0.0f;   // virtual B[base+0] = R[0][0] = 0
    }
    __syncthreads();

    const bool l0  = (lane == 0);
    const bool l31 = (lane == 31);
    // cost columns: rt -> 2L-1 (clamped for lane0; value discarded there),
    //               rA/rB pair -> float2 at 2L
    const int ccR = l0 ? 0 : (2 * lane - 1);
    const int cc2 = 2 * lane;

    // lane0 carry init: rt = B[base-1] (feeds rA's up at k=base)
    if (wid == 0 && l0) {
        const float* b0 = (const float*)&sbch[0][0];
        rt = b0[3];                         // B[base-1]
        ut = b0[2];                         // B[base-2] (unused for lane0)
    }

    int g = base;
#pragma unroll 1
    for (int gi = 0; gi < 133; ++gi, g += 16) {
        const int a = gi & 1;
        const int b = a ^ 1;

        if (wid == 0) {
            // ================= COMPUTE WARP =================
            const float* crd = &cbuf[a][0][0];
            const float* bb  = ((const float*)&sbch[a][0]) + 4;  // bb[p] = B[g+p]
            float  cRn = crd[ccR];
            float2 c2n = *(const float2*)(crd + cc2);
            float  bbn = bb[0];
            float  qv[16];

#pragma unroll
            for (int p = 0; p < 16; ++p) {
                float  cR = cRn;
                float2 c2 = c2n;
                float  bk = bbn;
                if (p < 15) {
                    cRn = crd[(p + 1) * 64 + ccR];
                    c2n = *(const float2*)(crd + (p + 1) * 64 + cc2);
                    bbn = bb[p + 1];
                }

                float rtold = rt;
                float rAold = rA;
                float shold = sh;

                // ---- phase 1: min/max networks, all three rows ----
                // row t: (shold, rtold, ut); row A: (rtold, rA, uA);
                // row B: (rAold, rB, uB)
                float w0 = fminf(shold, rtold), x0 = fmaxf(shold, rtold);
                float w1 = fminf(rtold, rA),    x1 = fmaxf(rtold, rA);
                float w2 = fminf(rAold, rB),    x2 = fmaxf(rAold, rB);
                float m0 = fminf(w0, ut),       y0 = fmaxf(w0, ut);
                float m1 = fminf(w1, uA),       y1 = fmaxf(w1, uA);
                float m2 = fminf(w2, uB),       y2 = fmaxf(w2, uB);

                // ---- phase 2: subs + off-chain cost+m ----
                float d0x = m0 - x0, d0y = m0 - y0;
                float d1x = m1 - x1, d1y = m1 - y1;
                float d2x = m2 - x2, d2y = m2 - y2;
                float cm0 = cR   + m0;
                float cm1 = c2.x + m1;
                float cm2 = c2.y + m2;

                // ---- phase 3: all ex2 back-to-back ----
                float e0x = ex2f(d0x), e0y = ex2f(d0y);
                float e1x = ex2f(d1x), e1y = ex2f(d1y);
                float e2x = ex2f(d2x), e2y = ex2f(d2y);

                // ---- phase 4: sums ----
                float s0 = (1.0f + e0x) + e0y;
                float s1 = (1.0f + e1x) + e1y;
                float s2 = (1.0f + e2x) + e2y;

                // ---- phase 5: all lg2 ----
                float t0 = lg2f(s0);
                float t1 = lg2f(s1);
                float t2 = lg2f(s2);

                // ---- phase 6: finals + carries ----
                rA = cm1 - t1;
                float shnew = __shfl_up_sync(0xffffffffu, rA, 1);
                rB = cm2 - t2;
                float rtnew = cm0 - t0;
                rt = l0 ? bk : rtnew;

                uA = rtold;
                uB = rAold;
                ut = shold;
                sh = shnew;

                qv[p] = rB;
            }

            if (gi == 132) res = qv[0];     // k = base+2112 (cta31: R[2048][2048])

            if (l31) {
                *(float4*)&obuf[a][0]  = make_float4(qv[0],  qv[1],  qv[2],  qv[3]);
                *(float4*)&obuf[a][4]  = make_float4(qv[4],  qv[5],  qv[6],  qv[7]);
                *(float4*)&obuf[a][8]  = make_float4(qv[8],  qv[9],  qv[10], qv[11]);
                *(float4*)&obuf[a][12] = make_float4(qv[12], qv[13], qv[14], qv[15]);
            }
        } else {
            // ================= HELPER WARP =================
            const int gnext = g + 16;
            // 1. publish group gi-1 (lane 0: release orders own prior stores)
            if (gi > 0 && lane == 0) {
                int gp = g - 16;
                float4 o0 = *(float4*)&obuf[b][0];
                float4 o1 = *(float4*)&obuf[b][4];
                float4 o2 = *(float4*)&obuf[b][8];
                float4 o3 = *(float4*)&obuf[b][12];
                stcg4(&g_bnd[cta][gp],      o0);
                stcg4(&g_bnd[cta][gp + 4],  o1);
                stcg4(&g_bnd[cta][gp + 8],  o2);
                stcg4(&g_bnd[cta][gp + 12], o3);
                rel_store(myflag, gp + 15);
            }
            // 2. cost LDGs for group gi+1
            const float* src = g_Cd + (size_t)gnext * CPITCH + base + qf;
            float4 tv[8];
#pragma unroll
            for (int j = 0; j < 8; ++j)
                tv[j] = __ldg((const float4*)(src + (size_t)(2 * j + ph) * CPITCH));
            // 3. acquire spin (off the critical warp)
            if (cta > 0) {
                int need = min(gnext + 15, flagmax);
                while (known < need) known = acq_load(pflag);
            }
            // 4. boundary chunks for gi+1
            if (lane < 5) {
                int cs = gnext - 4 + 4 * lane;
                sbch[b][lane] = (cta > 0 && cs <= wend) ? ldcg4(brow + cs) : BIG4;
            }
            // 5. STS costs
#pragma unroll
            for (int j = 0; j < 8; ++j)
                *(float4*)&cbuf[b][2 * j + ph][qf] = tv[j];
        }

        __syncthreads();
    }

    // epilogue: publish final group (132, in obuf[0]) for the successor
    if (wid == 1 && lane == 0) {
        int gp = base + 16 * 132;
        float4 o0 = *(float4*)&obuf[0][0];
        float4 o1 = *(float4*)&obuf[0][4];
        float4 o2 = *(float4*)&obuf[0][8];
        float4 o3 = *(float4*)&obuf[0][12];
        stcg4(&g_bnd[cta][gp],      o0);
        stcg4(&g_bnd[cta][gp + 4],  o1);
        stcg4(&g_bnd[cta][gp + 8],  o2);
        stcg4(&g_bnd[cta][gp + 12], o3);
        rel_store(myflag, gp + 15);
    }

    if (wid == 0 && cta == NCTA - 1 && l31) {
        out[0] = res * LN2F;
    }
}

// ---------------------------------------------------------------------------
extern "C" void kernel_launch(void* const* d_in, const int* in_sizes, int n_in,
                              void* d_out, int out_size) {
    const float* y  = (const float*)d_in[0];
    const float* x2 = (const float*)d_in[1];
    float* out = (float*)d_out;

    const int n4 = (CROWS * CPITCH) / 4;
    initc_k<<<(n4 + 1023) / 1024, 1024>>>();
    norms_k<<<512, 256>>>(y, x2);
    gemm_k<<<dim3(M2 / 64, M1 / 64), 256>>>(y, x2);
    dp_k<<<NCTA, 64>>>(out);
}